// round 1
// baseline (speedup 1.0000x reference)
#include <cuda_runtime.h>
#include <cstdint>

// Tropical (max-plus) depthwise 5x5 conv, B=8 C=32 H=W=224, stride=1, pad=2 (-inf), dil=1.
// out[b,c,y,x] = max_{i,j in [0,5)} xpad[b,c,y+i,x+j] + wflip[c,i,j]
// wflip[c,i,j] = kernel[c,0,4-i,4-j]

#define Hh 224
#define Ww 224
#define Cc 32
#define KK 5

constexpr int TILE = 32;          // output tile (square)
constexpr int SMH  = TILE + 4;    // 36 rows in smem (halo)
constexpr int SMW  = TILE + 4;    // 36 cols
constexpr int PITCH = 36;         // base pitch; skew (y>>2) added per row, monotone -> no overlap

__device__ __forceinline__ int saddr(int y, int col) {
    // Skewed address: bank = (4y + (y>>2) + col) mod 32.
    // For lane groups with y-offsets {0,4,8,12} this gives bank offsets {0,17,2,19},
    // distinct mod 4 -> conflict-free against x-offsets that are multiples of 4.
    return y * PITCH + col + (y >> 2);
}

__global__ __launch_bounds__(64) void tropical_dwconv(
    const float* __restrict__ x,
    const float* __restrict__ w,
    float* __restrict__ out)
{
    __shared__ float s[SMH * PITCH + 16];   // 36*36 + skew headroom (<= 36*37)
    __shared__ float wsm[25];

    const int tilesPerRow   = Ww / TILE;               // 7
    const int tilesPerPlane = tilesPerRow * (Hh/TILE); // 49
    const int plane = blockIdx.x / tilesPerPlane;
    const int t     = blockIdx.x - plane * tilesPerPlane;
    const int ty0   = (t / tilesPerRow) * TILE;
    const int tx0   = (t % tilesPerRow) * TILE;
    const int c     = plane & (Cc - 1);

    const float* __restrict__ xp = x + (size_t)plane * (Hh * Ww);
    const int tid = threadIdx.x;

    const float NEG_INF = __int_as_float(0xff800000u);

    // flipped weights for this channel
    if (tid < 25) {
        const int i = tid / 5, j = tid - 5 * i;
        wsm[tid] = w[c * 25 + (4 - i) * 5 + (4 - j)];
    }

    // load 36x36 input tile (with halo); OOB -> -inf
    #pragma unroll 4
    for (int idx = tid; idx < SMH * SMW; idx += 64) {
        const int r  = idx / SMW;
        const int cc = idx - r * SMW;
        const int gy = ty0 - 2 + r;
        const int gx = tx0 - 2 + cc;
        float v = NEG_INF;
        if ((unsigned)gy < (unsigned)Hh && (unsigned)gx < (unsigned)Ww)
            v = xp[gy * Ww + gx];
        s[saddr(r, cc)] = v;
    }
    __syncthreads();

    // weights to registers
    float wr[25];
    #pragma unroll
    for (int k = 0; k < 25; k++) wr[k] = wsm[k];

    // thread -> 4x4 output patch
    const int txq = (tid & 7) * 4;   // 0..28
    const int tyq = (tid >> 3) * 4;  // 0..28

    float acc[4][4];
    #pragma unroll
    for (int oy = 0; oy < 4; oy++)
        #pragma unroll
        for (int ox = 0; ox < 4; ox++)
            acc[oy][ox] = NEG_INF;

    // sliding window over 8 smem rows; each row feeds up to 4 output rows
    #pragma unroll
    for (int r = 0; r < 8; r++) {
        float v[8];
        #pragma unroll
        for (int k = 0; k < 8; k++)
            v[k] = s[saddr(tyq + r, txq + k)];

        #pragma unroll
        for (int oy = 0; oy < 4; oy++) {
            const int i = r - oy;             // compile-time per (r,oy)
            if (i >= 0 && i < KK) {
                #pragma unroll
                for (int j = 0; j < KK; j++) {
                    const float wv = wr[i * 5 + j];
                    #pragma unroll
                    for (int ox = 0; ox < 4; ox++)
                        acc[oy][ox] = fmaxf(acc[oy][ox], v[ox + j] + wv);
                }
            }
        }
    }

    // store: float4, 16B aligned (txq, tx0, Ww all multiples of 4)
    float* op = out + (size_t)plane * (Hh * Ww) + (size_t)(ty0 + tyq) * Ww + tx0 + txq;
    #pragma unroll
    for (int oy = 0; oy < 4; oy++) {
        float4 val = make_float4(acc[oy][0], acc[oy][1], acc[oy][2], acc[oy][3]);
        *reinterpret_cast<float4*>(op + oy * Ww) = val;
    }
}

extern "C" void kernel_launch(void* const* d_in, const int* in_sizes, int n_in,
                              void* d_out, int out_size) {
    const float* x = (const float*)d_in[0];          // (8,32,224,224) f32
    const float* w = (const float*)d_in[1];          // (32,1,5,5) f32
    float* out = (float*)d_out;

    const int planes = 8 * Cc;                       // 256
    const int tilesPerPlane = (Hh / TILE) * (Ww / TILE); // 49
    tropical_dwconv<<<planes * tilesPerPlane, 64>>>(x, w, out);
}

// round 2
// speedup vs baseline: 1.6810x; 1.6810x over previous
#include <cuda_runtime.h>
#include <cstdint>

// Tropical (max-plus) depthwise 5x5 conv, B=8 C=32 H=W=224, stride=1, pad=2 (-inf), dil=1.
// out[b,c,y,x] = max_{i,j} xpad[b,c,y+i,x+j] + wflip[c,i,j],  wflip[c,i,j] = kernel[c,0,4-i,4-j]

#define Hh 224
#define Ww 224
#define Cc 32

constexpr int TILE  = 32;    // square output tile
constexpr int SMH   = 36;    // rows incl. halo
constexpr int PITCH = 40;    // 2 slack cols left + 36 + 2 right; 16B-aligned rows

__global__ __launch_bounds__(64) void tropical_dwconv(
    const float* __restrict__ x,
    const float* __restrict__ w,
    float* __restrict__ out)
{
    __shared__ float s[SMH * PITCH];       // 5.76 KB
    __shared__ float wsm[25];

    const int tilesPerRow   = Ww / TILE;               // 7
    const int tilesPerPlane = tilesPerRow * (Hh/TILE); // 49
    const int plane = blockIdx.x / tilesPerPlane;
    const int t     = blockIdx.x - plane * tilesPerPlane;
    const int ty0   = (t / tilesPerRow) * TILE;
    const int tx0   = (t % tilesPerRow) * TILE;
    const int c     = plane & (Cc - 1);

    const float* __restrict__ xp = x + (size_t)plane * (Hh * Ww);
    const int tid = threadIdx.x;
    const float NEG_INF = __int_as_float(0xff800000u);

    if (tid < 25) {
        const int i = tid / 5, j = tid - 5 * i;
        wsm[tid] = w[c * 25 + (4 - i) * 5 + (4 - j)];
    }

    // ---- Tile load: 36 rows x 10 float4 per row = 360 vectors over 64 threads.
    // smem col p-layout: physical col pc corresponds to gx = tx0 - 4 + pc.
    // Vector at (row, c4): gx0 = tx0 - 4 + 4*c4 (16B aligned in gmem), store at pc = 4*c4.
    // Every float4 is fully in-bounds or fully OOB horizontally (224 % 4 == 0).
    const float4 NEGV = make_float4(NEG_INF, NEG_INF, NEG_INF, NEG_INF);
    #pragma unroll
    for (int k = 0; k < 6; k++) {
        const int idx = tid + 64 * k;
        if (idx < 360) {
            const unsigned row = (unsigned)idx / 10u;
            const int c4  = idx - (int)row * 10;
            const int gy  = ty0 - 2 + (int)row;
            const int gx0 = tx0 - 4 + 4 * c4;
            float4 v = NEGV;
            if ((unsigned)gy < (unsigned)Hh && (unsigned)gx0 <= (unsigned)(Ww - 4))
                v = *reinterpret_cast<const float4*>(xp + gy * Ww + gx0);
            *reinterpret_cast<float4*>(&s[row * PITCH + 4 * c4]) = v;
        }
    }
    __syncthreads();

    // weights to registers
    float wr[25];
    #pragma unroll
    for (int k = 0; k < 25; k++) wr[k] = wsm[k];

    // thread -> 4x4 output patch
    const int txq = (tid & 7) * 4;   // 0..28
    const int tyq = (tid >> 3) * 4;  // 0..28

    float acc[4][4];
    #pragma unroll
    for (int oy = 0; oy < 4; oy++)
        #pragma unroll
        for (int ox = 0; ox < 4; ox++)
            acc[oy][ox] = NEG_INF;

    // Output (y=ty0+tyq+oy, x=tx0+txq+ox) needs smem row tyq+oy+i, phys col txq+2+ox+j.
    // Read 12 elements per row via 3x LDS.128 starting at phys col txq (16B aligned):
    // vv[q] = phys col txq+q  ->  needed element for (ox,j) is vv[ox+j+2].
    #pragma unroll
    for (int r = 0; r < 8; r++) {
        const float* rp = &s[(tyq + r) * PITCH + txq];
        float4 va = *reinterpret_cast<const float4*>(rp);
        float4 vb = *reinterpret_cast<const float4*>(rp + 4);
        float4 vc = *reinterpret_cast<const float4*>(rp + 8);
        float vv[12] = {va.x, va.y, va.z, va.w,
                        vb.x, vb.y, vb.z, vb.w,
                        vc.x, vc.y, vc.z, vc.w};

        #pragma unroll
        for (int oy = 0; oy < 4; oy++) {
            const int i = r - oy;                 // compile-time after unroll
            if (i >= 0 && i < 5) {
                #pragma unroll
                for (int j = 0; j < 5; j++) {
                    const float wv = wr[i * 5 + j];
                    #pragma unroll
                    for (int ox = 0; ox < 4; ox++)
                        acc[oy][ox] = fmaxf(acc[oy][ox], vv[ox + j + 2] + wv);
                }
            }
        }
    }

    // store: float4, 16B aligned
    float* op = out + (size_t)plane * (Hh * Ww) + (size_t)(ty0 + tyq) * Ww + tx0 + txq;
    #pragma unroll
    for (int oy = 0; oy < 4; oy++) {
        float4 val = make_float4(acc[oy][0], acc[oy][1], acc[oy][2], acc[oy][3]);
        *reinterpret_cast<float4*>(op + oy * Ww) = val;
    }
}

extern "C" void kernel_launch(void* const* d_in, const int* in_sizes, int n_in,
                              void* d_out, int out_size) {
    const float* x = (const float*)d_in[0];          // (8,32,224,224) f32
    const float* w = (const float*)d_in[1];          // (32,1,5,5) f32
    float* out = (float*)d_out;

    const int planes = 8 * Cc;                           // 256
    const int tilesPerPlane = (Hh / TILE) * (Ww / TILE); // 49
    tropical_dwconv<<<planes * tilesPerPlane, 64>>>(x, w, out);
}

// round 8
// speedup vs baseline: 1.9035x; 1.1324x over previous
#include <cuda_runtime.h>
#include <cstdint>

// Tropical (max-plus) depthwise 5x5 conv, B=8 C=32 H=W=224, stride=1, pad=2 (-inf), dil=1.
// out[b,c,y,x] = max_{i,j} xpad[b,c,y+i,x+j] + wflip[c,i,j],  wflip[c,i,j] = kernel[c,0,4-i,4-j]

#define Hh 224
#define Ww 224
#define Cc 32

constexpr int TILE = 32;   // square output tile
constexpr int SMH  = 36;   // rows incl. halo
constexpr int PW   = 48;   // words per smem row (12 chunks of 16B; 10 used + swizzle headroom)

// XOR-swizzled chunk address (in words). Chunk = 16B = 4 words.
// Key (row>>2)&3 separates the four y-groups (rows 4 apart) into distinct banks.
__device__ __forceinline__ int swz(int row, int chunk) {
    return row * PW + 4 * (chunk ^ ((row >> 2) & 3));
}

__global__ __launch_bounds__(64) void tropical_dwconv(
    const float* __restrict__ x,
    const float* __restrict__ w,
    float* __restrict__ out)
{
    __shared__ float s[SMH * PW];      // 6.75 KB
    __shared__ float wsm[25];

    const int tilesPerRow   = Ww / TILE;               // 7
    const int tilesPerPlane = tilesPerRow * (Hh/TILE); // 49
    const int plane = blockIdx.x / tilesPerPlane;
    const int t     = blockIdx.x - plane * tilesPerPlane;
    const int ty0   = (t / tilesPerRow) * TILE;
    const int tx0   = (t % tilesPerRow) * TILE;
    const int c     = plane & (Cc - 1);

    const float* __restrict__ xp = x + (size_t)plane * (Hh * Ww);
    const int tid = threadIdx.x;
    const float NEG_INF = __int_as_float(0xff800000u);

    if (tid < 25) {
        const int i = tid / 5, j = tid - 5 * i;
        wsm[tid] = w[c * 25 + (4 - i) * 5 + (4 - j)];
    }

    // ---- Tile load: 36 rows x 10 float4 = 360 vectors over 64 threads.
    // Chunk c4 holds gx = tx0 - 4 + 4*c4 .. +3 (16B aligned in gmem).
    // Every float4 is fully in-bounds or fully OOB horizontally (224 % 4 == 0).
    const float4 NEGV = make_float4(NEG_INF, NEG_INF, NEG_INF, NEG_INF);
    #pragma unroll
    for (int k = 0; k < 6; k++) {
        const int idx = tid + 64 * k;
        if (idx < 360) {
            const int row = (int)((unsigned)idx / 10u);
            const int c4  = idx - row * 10;
            const int gy  = ty0 - 2 + row;
            const int gx0 = tx0 - 4 + 4 * c4;
            float4 v = NEGV;
            if ((unsigned)gy < (unsigned)Hh && (unsigned)gx0 <= (unsigned)(Ww - 4))
                v = *reinterpret_cast<const float4*>(xp + gy * Ww + gx0);
            *reinterpret_cast<float4*>(&s[swz(row, c4)]) = v;
        }
    }
    __syncthreads();

    // weights (block-uniform -> URs)
    float wr[25];
    #pragma unroll
    for (int k = 0; k < 25; k++) wr[k] = wsm[k];

    // thread -> 4x4 output patch
    const int txq = (tid & 7) * 4;   // 0..28
    const int tyq = (tid >> 3) * 4;  // 0..28
    const int c0  = txq >> 2;        // first chunk this thread reads
    const int g   = tyq >> 2;

    // Only two swizzle keys per thread: rows tyq..tyq+3 (key g&3) and rows
    // tyq+4..tyq+7 (key (g+1)&3). Precompute the six swizzled base pointers;
    // per-row LDS addresses are then [base + const].
    const float* baseA = &s[tyq * PW];
    const float* baseB = &s[(tyq + 4) * PW];
    const float* pA0 = baseA + 4 * ((c0 + 0) ^ (g & 3));
    const float* pA1 = baseA + 4 * ((c0 + 1) ^ (g & 3));
    const float* pA2 = baseA + 4 * ((c0 + 2) ^ (g & 3));
    const float* pB0 = baseB + 4 * ((c0 + 0) ^ ((g + 1) & 3));
    const float* pB1 = baseB + 4 * ((c0 + 1) ^ ((g + 1) & 3));
    const float* pB2 = baseB + 4 * ((c0 + 2) ^ ((g + 1) & 3));

    float acc[4][4];

    // Output (oy,ox) at global (ty0+tyq+oy, tx0+txq+ox) needs smem row tyq+oy+i,
    // logical col txq+2+ox+j -> vv[ox+j+2] where vv = 12 words starting at chunk c0.
    #pragma unroll
    for (int r = 0; r < 8; r++) {
        const int rr = (r < 4) ? r : (r - 4);        // compile-time
        float4 va, vb, vc;
        if (r < 4) {
            va = *reinterpret_cast<const float4*>(pA0 + rr * PW);
            vb = *reinterpret_cast<const float4*>(pA1 + rr * PW);
            vc = *reinterpret_cast<const float4*>(pA2 + rr * PW);
        } else {
            va = *reinterpret_cast<const float4*>(pB0 + rr * PW);
            vb = *reinterpret_cast<const float4*>(pB1 + rr * PW);
            vc = *reinterpret_cast<const float4*>(pB2 + rr * PW);
        }
        float vv[12] = {va.x, va.y, va.z, va.w,
                        vb.x, vb.y, vb.z, vb.w,
                        vc.x, vc.y, vc.z, vc.w};

        #pragma unroll
        for (int oy = 0; oy < 4; oy++) {
            const int i = r - oy;                    // compile-time
            if (i >= 0 && i < 5) {
                #pragma unroll
                for (int j = 0; j < 5; j++) {
                    const float wv = wr[i * 5 + j];
                    #pragma unroll
                    for (int ox = 0; ox < 4; ox++) {
                        if (i == 0 && j == 0)
                            acc[oy][ox] = vv[ox + 2] + wv;               // first tap: init
                        else
                            acc[oy][ox] = fmaxf(acc[oy][ox], vv[ox + j + 2] + wv);
                    }
                }
            }
        }
    }

    // store: float4, 16B aligned
    float* op = out + (size_t)plane * (Hh * Ww) + (size_t)(ty0 + tyq) * Ww + tx0 + txq;
    #pragma unroll
    for (int oy = 0; oy < 4; oy++) {
        float4 val = make_float4(acc[oy][0], acc[oy][1], acc[oy][2], acc[oy][3]);
        *reinterpret_cast<float4*>(op + oy * Ww) = val;
    }
}

extern "C" void kernel_launch(void* const* d_in, const int* in_sizes, int n_in,
                              void* d_out, int out_size) {
    const float* x = (const float*)d_in[0];          // (8,32,224,224) f32
    const float* w = (const float*)d_in[1];          // (32,1,5,5) f32
    float* out = (float*)d_out;

    const int planes = 8 * Cc;                           // 256
    const int tilesPerPlane = (Hh / TILE) * (Ww / TILE); // 49
    tropical_dwconv<<<planes * tilesPerPlane, 64>>>(x, w, out);
}